// round 14
// baseline (speedup 1.0000x reference)
#include <cuda_runtime.h>
#include <cuda_fp16.h>
#include <cstdint>
#include <cstddef>

#define E_TOT 150000
#define TE    64          // rows per CTA tile
#define NT    128         // 4 warps = 2 m-groups x 2 n-groups
#define SA    136         // fp16 padded row stride (elements)
#define RB    272         // row bytes

// ---- smem layout (bytes) ----
#define OFF_VEC  0                       // 7 x 128 fp16 = 1792
#define OFF_PART 1792                    // 2 x 64 float2 = 1024
#define OFF_A    2816                    // 64*272 = 17408
#define OFF_W    20224                   // single fp16: 128*272 = 34816
#define SMEM_SZ  55040                   // -> 4 CTAs/SM

// pre-rounded weights: 27 matrices, fp16, padded layout identical to smem
__device__ __align__(16) __half g_w[27][128 * SA];
// pre-rounded x: fp16, linear [row][col]
__device__ __align__(16) __half g_x[(size_t)E_TOT * 128];

// ---------------------------------------------------------------------------
__device__ __forceinline__ uint32_t pkh(float a, float b) {
    __half2 t = __floats2half2_rn(a, b);
    return *(uint32_t*)&t;
}
__device__ __forceinline__ uint32_t s2u(const void* p) {
    uint32_t a;
    asm("{ .reg .u64 t; cvta.to.shared.u64 t, %1; cvt.u32.u64 %0, t; }" : "=r"(a) : "l"(p));
    return a;
}
__device__ __forceinline__ void cpa16(uint32_t saddr, const void* g) {
    asm volatile("cp.async.cg.shared.global [%0], [%1], 16;" :: "r"(saddr), "l"(g));
}
__device__ __forceinline__ void cpa_commit() { asm volatile("cp.async.commit_group;" ::: "memory"); }

__device__ __forceinline__ void mma16816(float d[4], const uint32_t a[4],
                                         uint32_t b0, uint32_t b1) {
    asm volatile(
        "mma.sync.aligned.m16n8k16.row.col.f32.f16.f16.f32 "
        "{%0,%1,%2,%3}, {%4,%5,%6,%7}, {%8,%9}, {%0,%1,%2,%3};\n"
        : "+f"(d[0]), "+f"(d[1]), "+f"(d[2]), "+f"(d[3])
        : "r"(a[0]), "r"(a[1]), "r"(a[2]), "r"(a[3]), "r"(b0), "r"(b1));
}
#define LDSM4(r, addr) \
    asm volatile("ldmatrix.sync.aligned.m8n8.x4.shared.b16 {%0,%1,%2,%3}, [%4];" \
        : "=r"((r)[0]), "=r"((r)[1]), "=r"((r)[2]), "=r"((r)[3]) : "r"(addr))

__device__ __forceinline__ float tanhf_fast(float x) {
    float r; asm("tanh.approx.f32 %0, %1;" : "=f"(r) : "f"(x)); return r;
}
__device__ __forceinline__ float silu(float y) {
    return y * fmaf(0.5f, tanhf_fast(0.5f * y), 0.5f);
}

// ---------------------------------------------------------------------------
// prep (single kernel): blocks [0,27) round weights; blocks [27,...) round x
// ---------------------------------------------------------------------------
__global__ void prep_all(const float* __restrict__ x,
                         const float* __restrict__ W1,
                         const float* __restrict__ ef2w, const float* __restrict__ f2w,
                         const float* __restrict__ ef3w, const float* __restrict__ f3w) {
    if (blockIdx.x < 27) {
        int m = blockIdx.x;
        const float* src;
        if (m < 9)       src = W1 + (size_t)m * 16384;
        else if (m < 18) { int b = m - 9;  src = b ? f2w + (size_t)(b - 1) * 16384 : ef2w; }
        else             { int b = m - 18; src = b ? f3w + (size_t)(b - 1) * 16384 : ef3w; }
        __half* w = g_w[m];
        for (int i = threadIdx.x; i < 16384; i += 256) {
            int r = i >> 7, c = i & 127;
            w[r * SA + c] = __float2half_rn(__ldg(src + i));
        }
        return;
    }
    size_t i = (size_t)(blockIdx.x - 27) * 256 + threadIdx.x;  // one float4 per thread
    if (i >= (size_t)E_TOT * 32) return;
    float4 v = __ldg((const float4*)x + i);
    uint2 uh;
    uh.x = pkh(v.x, v.y);
    uh.y = pkh(v.z, v.w);
    *(uint2*)(g_x + i * 4) = uh;
}

// ---------------------------------------------------------------------------
// 64x128x128 GEMM from smem via ldmatrix, m32n64 warp tiles:
// 4 warps = 2 m-groups (warp>>1) x 2 n-groups (warp&1).
// Per k-step: 2 a-LDSM.x4 + 4 b-LDSM.x4 feed 16 HMMA (1.5 wf/HMMA).
// ---------------------------------------------------------------------------
__device__ __forceinline__ void gemm64(uint32_t sb, float acc[2][8][4], int warp, int lane) {
#pragma unroll
    for (int mi = 0; mi < 2; mi++)
#pragma unroll
        for (int nj = 0; nj < 8; nj++)
#pragma unroll
            for (int j = 0; j < 4; j++) acc[mi][nj][j] = 0.f;

    const int mblk = (warp >> 1) << 5;
    const int nblk = (warp & 1) << 6;

    const int rs_a = (lane & 7) + (((lane >> 3) & 1) << 3);
    const uint32_t ka = (lane >> 4) << 4;
    const uint32_t a0 = sb + OFF_A + (mblk + rs_a) * RB + ka;      // m16 block 0
    const uint32_t a1 = a0 + 16 * RB;                              // m16 block 1
    const int rs_b = (lane & 7) + ((lane >> 4) << 3);
    const uint32_t kb = ((lane >> 3) & 1) << 4;
    const uint32_t bb = sb + OFF_W + (nblk + rs_b) * RB + kb;      // n16 group base

#pragma unroll 1
    for (int ks = 0; ks < 8; ks++) {
        const uint32_t k0b = ks << 5;                              // 16 elems = 32B
        uint32_t ah0[4], ah1[4];
        uint32_t bf[4][4];
        LDSM4(ah0, a0 + k0b);
        LDSM4(ah1, a1 + k0b);
#pragma unroll
        for (int p = 0; p < 4; p++)
            LDSM4(bf[p], bb + p * (16 * RB) + k0b);

#pragma unroll
        for (int p = 0; p < 4; p++) {
            mma16816(acc[0][2 * p],     ah0, bf[p][0], bf[p][1]);
            mma16816(acc[0][2 * p + 1], ah0, bf[p][2], bf[p][3]);
            mma16816(acc[1][2 * p],     ah1, bf[p][0], bf[p][1]);
            mma16816(acc[1][2 * p + 1], ah1, bf[p][2], bf[p][3]);
        }
    }
}

// ---------------------------------------------------------------------------
// LN+SiLU epilogue: bias add, row stats (quad-shfl + 2-ngroup partials),
// normalize, fp16 -> A buffer. Internal __syncthreads.
// Lane owns rows mblk + grp + {0,8,16,24}; cols nblk + nj*8 + tig*2 (nj 0..7).
// Per-branch vectors are fp16 (half2 loads, c is always even).
// ---------------------------------------------------------------------------
__device__ __forceinline__ void epilogue_ln(char* sm, float acc[2][8][4], int vecb,
                                            int warp, int lane) {
    const int tig  = lane & 3;
    const int grp  = lane >> 2;
    const int ngrp = warp & 1;
    const int mblk = (warp >> 1) << 5;
    const int nblk = ngrp << 6;

    const __half* vec  = (const __half*)(sm + OFF_VEC);
    const __half* bias = vec + vecb * 128;
    const __half* lw   = bias + 128;
    const __half* lb   = bias + 256;

    float s[4] = {0.f, 0.f, 0.f, 0.f};
    float q[4] = {0.f, 0.f, 0.f, 0.f};
#pragma unroll
    for (int mi = 0; mi < 2; mi++) {
#pragma unroll
        for (int nj = 0; nj < 8; nj++) {
            const int c = nblk + (nj << 3) + (tig << 1);
            const float2 b01 = __half22float2(*(const __half2*)(bias + c));
            float* a = acc[mi][nj];
            a[0] += b01.x; a[1] += b01.y; a[2] += b01.x; a[3] += b01.y;
            s[2 * mi]     += a[0] + a[1];
            q[2 * mi]      = fmaf(a[0], a[0], fmaf(a[1], a[1], q[2 * mi]));
            s[2 * mi + 1] += a[2] + a[3];
            q[2 * mi + 1]  = fmaf(a[2], a[2], fmaf(a[3], a[3], q[2 * mi + 1]));
        }
    }
#pragma unroll
    for (int off = 1; off <= 2; off <<= 1) {
#pragma unroll
        for (int i = 0; i < 4; i++) {
            s[i] += __shfl_xor_sync(0xFFFFFFFFu, s[i], off);
            q[i] += __shfl_xor_sync(0xFFFFFFFFu, q[i], off);
        }
    }
    float2* part = (float2*)(sm + OFF_PART);
    if (tig == 0) {
        part[ngrp * 64 + mblk + grp]      = make_float2(s[0], q[0]);
        part[ngrp * 64 + mblk + grp + 8]  = make_float2(s[1], q[1]);
        part[ngrp * 64 + mblk + grp + 16] = make_float2(s[2], q[2]);
        part[ngrp * 64 + mblk + grp + 24] = make_float2(s[3], q[3]);
    }
    __syncthreads();
    float m[4], inv[4];
#pragma unroll
    for (int i = 0; i < 4; i++) {
        const int row = mblk + grp + (i << 3);
        float2 p0 = part[row];
        float2 p1 = part[64 + row];
        const float ss = p0.x + p1.x, qq = p0.y + p1.y;
        m[i]   = ss * (1.0f / 128.0f);
        inv[i] = rsqrtf(fmaf(-m[i], m[i], qq * (1.0f / 128.0f)) + 1e-5f);
    }

#pragma unroll
    for (int mi = 0; mi < 2; mi++) {
        const int i0 = 2 * mi, i1 = 2 * mi + 1;
        const int r0 = mblk + grp + (mi << 4);
        const int r1 = r0 + 8;
#pragma unroll
        for (int nj = 0; nj < 8; nj++) {
            const int c = nblk + (nj << 3) + (tig << 1);
            const float2 wv = __half22float2(*(const __half2*)(lw + c));
            const float2 bv = __half22float2(*(const __half2*)(lb + c));
            const float* a = acc[mi][nj];
            float y00 = silu((a[0] - m[i0]) * inv[i0] * wv.x + bv.x);
            float y01 = silu((a[1] - m[i0]) * inv[i0] * wv.y + bv.y);
            float y10 = silu((a[2] - m[i1]) * inv[i1] * wv.x + bv.x);
            float y11 = silu((a[3] - m[i1]) * inv[i1] * wv.y + bv.y);
            *(uint32_t*)(sm + OFF_A + r0 * RB + c * 2) = pkh(y00, y01);
            *(uint32_t*)(sm + OFF_A + r1 * RB + c * 2) = pkh(y10, y11);
        }
    }
}

__device__ __forceinline__ void cp_weights(uint32_t sdst, int m, int tid) {
    const char* g = (const char*)g_w[m];               // 34816B fp16
    for (int i = tid; i < 34816 / 16; i += NT)
        cpa16(sdst + i * 16, g + (size_t)i * 16);
    cpa_commit();
}

// ---------------------------------------------------------------------------
extern __shared__ char smraw[];

__global__ void __launch_bounds__(NT, 4)
urmlp_kernel(const float* __restrict__ b1c,
             const float* __restrict__ eln1w, const float* __restrict__ eln1b,
             const float* __restrict__ ef2b,
             const float* __restrict__ eln2w, const float* __restrict__ eln2b,
             const float* __restrict__ ef3b,
             const float* __restrict__ ln1w,  const float* __restrict__ ln1b,
             const float* __restrict__ f2b,
             const float* __restrict__ ln2w,  const float* __restrict__ ln2b,
             const float* __restrict__ f3b,
             float* __restrict__ out)
{
    char* sm = smraw;
    const int tid  = threadIdx.x;
    const int warp = tid >> 5;
    const int lane = tid & 31;
    const int bid  = blockIdx.x;
    const int tile = bid / 9;
    const int br   = bid - tile * 9;
    const int base = tile * TE;
    const int nvalid = min(TE, E_TOT - base);
    const uint32_t sb = s2u(sm);

    // g1: W1 -> W buf
    cp_weights(sb + OFF_W, br, tid);

    // g2: x tile -> A; zero-fill invalid rows
    {
        for (int i = tid; i < TE * 16; i += NT) {       // 16 x 16B chunks per row
            const int row = i >> 4, ch = i & 15;
            const uint32_t dh = sb + OFF_A + row * RB + ch * 16;
            if (row < nvalid) {
                cpa16(dh, g_x + (size_t)(base + row) * 128 + ch * 8);
            } else {
                *(uint4*)(sm + OFF_A + row * RB + ch * 16) = make_uint4(0, 0, 0, 0);
            }
        }
        cpa_commit();
    }

    // per-branch vectors (fp16): [b1, lw1, lb1, b2, lw2, lb2, b3]
    {
        __half* vec = (__half*)(sm + OFF_VEC);
        const float* s0 = b1c + br * 128;
        const float* s1 = br ? ln1w + (br - 1) * 128 : eln1w;
        const float* s2 = br ? ln1b + (br - 1) * 128 : eln1b;
        const float* s3 = br ? f2b  + (br - 1) * 128 : ef2b;
        const float* s4 = br ? ln2w + (br - 1) * 128 : eln2w;
        const float* s5 = br ? ln2b + (br - 1) * 128 : eln2b;
        const float* s6 = br ? f3b  + (br - 1) * 128 : ef3b;
        vec[0 * 128 + tid] = __float2half_rn(__ldg(s0 + tid));
        vec[1 * 128 + tid] = __float2half_rn(__ldg(s1 + tid));
        vec[2 * 128 + tid] = __float2half_rn(__ldg(s2 + tid));
        vec[3 * 128 + tid] = __float2half_rn(__ldg(s3 + tid));
        vec[4 * 128 + tid] = __float2half_rn(__ldg(s4 + tid));
        vec[5 * 128 + tid] = __float2half_rn(__ldg(s5 + tid));
        vec[6 * 128 + tid] = __float2half_rn(__ldg(s6 + tid));
    }

    asm volatile("cp.async.wait_group 0;" ::: "memory");
    __syncthreads();

    float acc[2][8][4];

    // ---- stage 1 ----
    gemm64(sb, acc, warp, lane);
    __syncthreads();                    // all reads of a/w done
    cp_weights(sb + OFF_W, 9 + br, tid);   // W2, overlaps epilogue
    epilogue_ln(sm, acc, 0, warp, lane);
    asm volatile("cp.async.wait_group 0;" ::: "memory");
    __syncthreads();

    // ---- stage 2 ----
    gemm64(sb, acc, warp, lane);
    __syncthreads();
    cp_weights(sb + OFF_W, 18 + br, tid);  // W3
    epilogue_ln(sm, acc, 3, warp, lane);
    asm volatile("cp.async.wait_group 0;" ::: "memory");
    __syncthreads();

    // ---- stage 3: out = h @ fc3^T + b3 ----
    gemm64(sb, acc, warp, lane);
    {
        const int tig  = lane & 3;
        const int grp  = lane >> 2;
        const int mblk = (warp >> 1) << 5;
        const int nblk = (warp & 1) << 6;
        const __half* bias = (const __half*)(sm + OFF_VEC) + 6 * 128;
#pragma unroll
        for (int mi = 0; mi < 2; mi++) {
            const int r0 = mblk + grp + (mi << 4);
            const int r1 = r0 + 8;
            float* o0 = out + ((size_t)br * E_TOT + base + r0) * 128;
            float* o1 = o0 + (size_t)8 * 128;
#pragma unroll
            for (int nj = 0; nj < 8; nj++) {
                const int c = nblk + (nj << 3) + (tig << 1);
                const float2 b01 = __half22float2(*(const __half2*)(bias + c));
                const float* a = acc[mi][nj];
                if (r0 < nvalid)
                    *(float2*)(o0 + c) = make_float2(a[0] + b01.x, a[1] + b01.y);
                if (r1 < nvalid)
                    *(float2*)(o1 + c) = make_float2(a[2] + b01.x, a[3] + b01.y);
            }
        }
    }
}

extern "C" void kernel_launch(void* const* d_in, const int* in_sizes, int n_in,
                              void* d_out, int out_size) {
    const float* x     = (const float*)d_in[0];
    const float* W1    = (const float*)d_in[1];
    const float* b1    = (const float*)d_in[2];
    const float* eln1w = (const float*)d_in[3];
    const float* eln1b = (const float*)d_in[4];
    const float* ef2w  = (const float*)d_in[5];
    const float* ef2b  = (const float*)d_in[6];
    const float* eln2w = (const float*)d_in[7];
    const float* eln2b = (const float*)d_in[8];
    const float* ef3w  = (const float*)d_in[9];
    const float* ef3b  = (const float*)d_in[10];
    const float* ln1w  = (const float*)d_in[11];
    const float* ln1b  = (const float*)d_in[12];
    const float* f2w   = (const float*)d_in[13];
    const float* f2b   = (const float*)d_in[14];
    const float* ln2w  = (const float*)d_in[15];
    const float* ln2b  = (const float*)d_in[16];
    const float* f3w   = (const float*)d_in[17];
    const float* f3b   = (const float*)d_in[18];
    float* out = (float*)d_out;

    cudaFuncSetAttribute(urmlp_kernel, cudaFuncAttributeMaxDynamicSharedMemorySize, SMEM_SZ);

    const int xblocks = (E_TOT * 32 + 255) / 256;
    prep_all<<<27 + xblocks, 256>>>(x, W1, ef2w, f2w, ef3w, f3w);

    const int tiles = (E_TOT + TE - 1) / TE;   // 2344
    urmlp_kernel<<<tiles * 9, NT, SMEM_SZ>>>(
        b1, eln1w, eln1b, ef2b, eln2w, eln2b, ef3b,
        ln1w, ln1b, f2b, ln2w, ln2b, f3b, out);
}

// round 15
// speedup vs baseline: 1.0202x; 1.0202x over previous
#include <cuda_runtime.h>
#include <cuda_fp16.h>
#include <cstdint>
#include <cstddef>

#define E_TOT 150000
#define TE    128         // rows per CTA tile
#define NT    256         // 8 warps = 4 m-groups x 2 n-groups
#define SA    136         // fp16 padded row stride (elements)
#define RB    272         // row bytes

// ---- smem layout (bytes) ----
#define OFF_VEC  0                       // 7 x 128 f32 = 3584
#define OFF_PART 3584                    // 2 x 128 float2 = 2048
#define OFF_A    5632                    // 128*272 = 34816
#define OFF_W0   (OFF_A + 34816)         // fp16 weight buf0: 34816
#define OFF_W1   (OFF_W0 + 34816)        // fp16 weight buf1: 34816
#define SMEM_SZ  (OFF_W1 + 34816)        // 110080 -> 2 CTAs/SM

// pre-rounded weights: 27 matrices, fp16, padded layout identical to smem
__device__ __align__(16) __half g_w[27][128 * SA];
// pre-rounded x: fp16, linear [row][col]
__device__ __align__(16) __half g_x[(size_t)E_TOT * 128];

// ---------------------------------------------------------------------------
__device__ __forceinline__ uint32_t pkh(float a, float b) {
    __half2 t = __floats2half2_rn(a, b);
    return *(uint32_t*)&t;
}
__device__ __forceinline__ uint32_t s2u(const void* p) {
    uint32_t a;
    asm("{ .reg .u64 t; cvta.to.shared.u64 t, %1; cvt.u32.u64 %0, t; }" : "=r"(a) : "l"(p));
    return a;
}
__device__ __forceinline__ void cpa16(uint32_t saddr, const void* g) {
    asm volatile("cp.async.cg.shared.global [%0], [%1], 16;" :: "r"(saddr), "l"(g));
}
__device__ __forceinline__ void cpa_commit() { asm volatile("cp.async.commit_group;" ::: "memory"); }

__device__ __forceinline__ void mma16816(float d[4], const uint32_t a[4],
                                         uint32_t b0, uint32_t b1) {
    asm volatile(
        "mma.sync.aligned.m16n8k16.row.col.f32.f16.f16.f32 "
        "{%0,%1,%2,%3}, {%4,%5,%6,%7}, {%8,%9}, {%0,%1,%2,%3};\n"
        : "+f"(d[0]), "+f"(d[1]), "+f"(d[2]), "+f"(d[3])
        : "r"(a[0]), "r"(a[1]), "r"(a[2]), "r"(a[3]), "r"(b0), "r"(b1));
}
#define LDSM4(r, addr) \
    asm volatile("ldmatrix.sync.aligned.m8n8.x4.shared.b16 {%0,%1,%2,%3}, [%4];" \
        : "=r"((r)[0]), "=r"((r)[1]), "=r"((r)[2]), "=r"((r)[3]) : "r"(addr))

__device__ __forceinline__ float tanhf_fast(float x) {
    float r; asm("tanh.approx.f32 %0, %1;" : "=f"(r) : "f"(x)); return r;
}
__device__ __forceinline__ float silu(float y) {
    return y * fmaf(0.5f, tanhf_fast(0.5f * y), 0.5f);
}

// ---------------------------------------------------------------------------
// prep (single kernel): blocks [0,27) round weights; blocks [27,...) round x
// ---------------------------------------------------------------------------
__global__ void prep_all(const float* __restrict__ x,
                         const float* __restrict__ W1,
                         const float* __restrict__ ef2w, const float* __restrict__ f2w,
                         const float* __restrict__ ef3w, const float* __restrict__ f3w) {
    if (blockIdx.x < 27) {
        int m = blockIdx.x;
        const float* src;
        if (m < 9)       src = W1 + (size_t)m * 16384;
        else if (m < 18) { int b = m - 9;  src = b ? f2w + (size_t)(b - 1) * 16384 : ef2w; }
        else             { int b = m - 18; src = b ? f3w + (size_t)(b - 1) * 16384 : ef3w; }
        __half* w = g_w[m];
        for (int i = threadIdx.x; i < 16384; i += 256) {
            int r = i >> 7, c = i & 127;
            w[r * SA + c] = __float2half_rn(__ldg(src + i));
        }
        return;
    }
    size_t i = (size_t)(blockIdx.x - 27) * 256 + threadIdx.x;  // one float4 per thread
    if (i >= (size_t)E_TOT * 32) return;
    float4 v = __ldg((const float4*)x + i);
    uint2 uh;
    uh.x = pkh(v.x, v.y);
    uh.y = pkh(v.z, v.w);
    *(uint2*)(g_x + i * 4) = uh;
}

// ---------------------------------------------------------------------------
// 128x128x128 GEMM from smem via ldmatrix, m32n64 warp tiles:
// 8 warps = 4 m-groups (warp>>1) x 2 n-groups (warp&1).
// Per k-step: 2 a-LDSM.x4 + 4 b-LDSM.x4 feed 16 HMMA (1.5 wf/HMMA).
// ---------------------------------------------------------------------------
__device__ __forceinline__ void gemm128(uint32_t sb, uint32_t wbase,
                                        float acc[2][8][4], int warp, int lane) {
#pragma unroll
    for (int mi = 0; mi < 2; mi++)
#pragma unroll
        for (int nj = 0; nj < 8; nj++)
#pragma unroll
            for (int j = 0; j < 4; j++) acc[mi][nj][j] = 0.f;

    const int mblk = (warp >> 1) << 5;
    const int nblk = (warp & 1) << 6;

    const int rs_a = (lane & 7) + (((lane >> 3) & 1) << 3);
    const uint32_t ka = (lane >> 4) << 4;
    const uint32_t a0 = sb + OFF_A + (mblk + rs_a) * RB + ka;      // m16 block 0
    const uint32_t a1 = a0 + 16 * RB;                              // m16 block 1
    const int rs_b = (lane & 7) + ((lane >> 4) << 3);
    const uint32_t kb = ((lane >> 3) & 1) << 4;
    const uint32_t bb = wbase + (nblk + rs_b) * RB + kb;           // n16 group base

#pragma unroll 1
    for (int ks = 0; ks < 8; ks++) {
        const uint32_t k0b = ks << 5;                              // 16 elems = 32B
        uint32_t ah0[4], ah1[4];
        uint32_t bf[4][4];
        LDSM4(ah0, a0 + k0b);
        LDSM4(ah1, a1 + k0b);
#pragma unroll
        for (int p = 0; p < 4; p++)
            LDSM4(bf[p], bb + p * (16 * RB) + k0b);

#pragma unroll
        for (int p = 0; p < 4; p++) {
            mma16816(acc[0][2 * p],     ah0, bf[p][0], bf[p][1]);
            mma16816(acc[0][2 * p + 1], ah0, bf[p][2], bf[p][3]);
            mma16816(acc[1][2 * p],     ah1, bf[p][0], bf[p][1]);
            mma16816(acc[1][2 * p + 1], ah1, bf[p][2], bf[p][3]);
        }
    }
}

// ---------------------------------------------------------------------------
// LN+SiLU epilogue: bias add, row stats (quad-shfl + 2-ngroup partials),
// normalize, fp16 -> A buffer. Internal __syncthreads.
// ---------------------------------------------------------------------------
__device__ __forceinline__ void epilogue_ln(char* sm, float acc[2][8][4], int vecb,
                                            int warp, int lane) {
    const int tig  = lane & 3;
    const int grp  = lane >> 2;
    const int ngrp = warp & 1;
    const int mblk = (warp >> 1) << 5;
    const int nblk = ngrp << 6;

    const float* vec  = (const float*)(sm + OFF_VEC);
    const float* bias = vec + vecb * 128;
    const float* lw   = bias + 128;
    const float* lb   = bias + 256;

    float s[4] = {0.f, 0.f, 0.f, 0.f};
    float q[4] = {0.f, 0.f, 0.f, 0.f};
#pragma unroll
    for (int mi = 0; mi < 2; mi++) {
#pragma unroll
        for (int nj = 0; nj < 8; nj++) {
            const int c = nblk + (nj << 3) + (tig << 1);
            const float b0 = bias[c], b1 = bias[c + 1];
            float* a = acc[mi][nj];
            a[0] += b0; a[1] += b1; a[2] += b0; a[3] += b1;
            s[2 * mi]     += a[0] + a[1];
            q[2 * mi]      = fmaf(a[0], a[0], fmaf(a[1], a[1], q[2 * mi]));
            s[2 * mi + 1] += a[2] + a[3];
            q[2 * mi + 1]  = fmaf(a[2], a[2], fmaf(a[3], a[3], q[2 * mi + 1]));
        }
    }
#pragma unroll
    for (int off = 1; off <= 2; off <<= 1) {
#pragma unroll
        for (int i = 0; i < 4; i++) {
            s[i] += __shfl_xor_sync(0xFFFFFFFFu, s[i], off);
            q[i] += __shfl_xor_sync(0xFFFFFFFFu, q[i], off);
        }
    }
    float2* part = (float2*)(sm + OFF_PART);
    if (tig == 0) {
        part[ngrp * 128 + mblk + grp]      = make_float2(s[0], q[0]);
        part[ngrp * 128 + mblk + grp + 8]  = make_float2(s[1], q[1]);
        part[ngrp * 128 + mblk + grp + 16] = make_float2(s[2], q[2]);
        part[ngrp * 128 + mblk + grp + 24] = make_float2(s[3], q[3]);
    }
    __syncthreads();
    float m[4], inv[4];
#pragma unroll
    for (int i = 0; i < 4; i++) {
        const int row = mblk + grp + (i << 3);
        float2 p0 = part[row];
        float2 p1 = part[128 + row];
        const float ss = p0.x + p1.x, qq = p0.y + p1.y;
        m[i]   = ss * (1.0f / 128.0f);
        inv[i] = rsqrtf(fmaf(-m[i], m[i], qq * (1.0f / 128.0f)) + 1e-5f);
    }

#pragma unroll
    for (int mi = 0; mi < 2; mi++) {
        const int i0 = 2 * mi, i1 = 2 * mi + 1;
        const int r0 = mblk + grp + (mi << 4);
        const int r1 = r0 + 8;
#pragma unroll
        for (int nj = 0; nj < 8; nj++) {
            const int c = nblk + (nj << 3) + (tig << 1);
            const float w0 = lw[c], w1 = lw[c + 1], c0 = lb[c], c1 = lb[c + 1];
            const float* a = acc[mi][nj];
            float y00 = silu((a[0] - m[i0]) * inv[i0] * w0 + c0);
            float y01 = silu((a[1] - m[i0]) * inv[i0] * w1 + c1);
            float y10 = silu((a[2] - m[i1]) * inv[i1] * w0 + c0);
            float y11 = silu((a[3] - m[i1]) * inv[i1] * w1 + c1);
            *(uint32_t*)(sm + OFF_A + r0 * RB + c * 2) = pkh(y00, y01);
            *(uint32_t*)(sm + OFF_A + r1 * RB + c * 2) = pkh(y10, y11);
        }
    }
}

__device__ __forceinline__ void cp_weights(uint32_t sdst, int m, int tid) {
    const char* g = (const char*)g_w[m];               // 34816B fp16
    for (int i = tid; i < 34816 / 16; i += NT)
        cpa16(sdst + i * 16, g + (size_t)i * 16);
    cpa_commit();
}

// ---------------------------------------------------------------------------
extern __shared__ char smraw[];

__global__ void __launch_bounds__(NT, 2)
urmlp_kernel(const float* __restrict__ b1c,
             const float* __restrict__ eln1w, const float* __restrict__ eln1b,
             const float* __restrict__ ef2b,
             const float* __restrict__ eln2w, const float* __restrict__ eln2b,
             const float* __restrict__ ef3b,
             const float* __restrict__ ln1w,  const float* __restrict__ ln1b,
             const float* __restrict__ f2b,
             const float* __restrict__ ln2w,  const float* __restrict__ ln2b,
             const float* __restrict__ f3b,
             float* __restrict__ out)
{
    char* sm = smraw;
    const int tid  = threadIdx.x;
    const int warp = tid >> 5;
    const int lane = tid & 31;
    const int bid  = blockIdx.x;
    const int tile = bid / 9;
    const int br   = bid - tile * 9;
    const int base = tile * TE;
    const int nvalid = min(TE, E_TOT - base);
    const uint32_t sb = s2u(sm);

    // Phase stagger: second co-resident slot (wave-0 bids 148..295) delays
    // ~half a stage so the two CTAs on an SM anti-phase gemm vs epilogue.
    if (bid >= 148 && bid < 296) {
        unsigned long long t0 = clock64();
        while (clock64() - t0 < 4096ull) { }
    }

    // g0: W1 -> buf0
    cp_weights(sb + OFF_W0, br, tid);

    // g1: x tile -> A; zero-fill invalid rows
    {
        for (int i = tid; i < TE * 16; i += NT) {       // 16 x 16B chunks per row
            const int row = i >> 4, ch = i & 15;
            const uint32_t dh = sb + OFF_A + row * RB + ch * 16;
            if (row < nvalid) {
                cpa16(dh, g_x + (size_t)(base + row) * 128 + ch * 8);
            } else {
                *(uint4*)(sm + OFF_A + row * RB + ch * 16) = make_uint4(0, 0, 0, 0);
            }
        }
        cpa_commit();
    }

    // g2: W2 -> buf1 (prefetch, covered by gemm1)
    cp_weights(sb + OFF_W1, 9 + br, tid);

    // per-branch vectors: [b1, lw1, lb1, b2, lw2, lb2, b3]
    if (tid < 128) {
        float* vec = (float*)(sm + OFF_VEC);
        const float* s0 = b1c + br * 128;
        const float* s1 = br ? ln1w + (br - 1) * 128 : eln1w;
        const float* s2 = br ? ln1b + (br - 1) * 128 : eln1b;
        const float* s3 = br ? f2b  + (br - 1) * 128 : ef2b;
        const float* s4 = br ? ln2w + (br - 1) * 128 : eln2w;
        const float* s5 = br ? ln2b + (br - 1) * 128 : eln2b;
        const float* s6 = br ? f3b  + (br - 1) * 128 : ef3b;
        vec[0 * 128 + tid] = __ldg(s0 + tid);
        vec[1 * 128 + tid] = __ldg(s1 + tid);
        vec[2 * 128 + tid] = __ldg(s2 + tid);
        vec[3 * 128 + tid] = __ldg(s3 + tid);
        vec[4 * 128 + tid] = __ldg(s4 + tid);
        vec[5 * 128 + tid] = __ldg(s5 + tid);
        vec[6 * 128 + tid] = __ldg(s6 + tid);
    }

    asm volatile("cp.async.wait_group 1;" ::: "memory");   // g0,g1 done; g2 in flight
    __syncthreads();

    float acc[2][8][4];

    // ---- stage 1: buf0 ----
    gemm128(sb, sb + OFF_W0, acc, warp, lane);
    __syncthreads();                    // all reads of A/W0 done
    cp_weights(sb + OFF_W0, 18 + br, tid);   // g3: W3 -> buf0 (covered by epi1+gemm2)
    epilogue_ln(sm, acc, 0, warp, lane);
    asm volatile("cp.async.wait_group 1;" ::: "memory");   // g2 (W2) done; g3 in flight
    __syncthreads();

    // ---- stage 2: buf1 ----
    gemm128(sb, sb + OFF_W1, acc, warp, lane);
    __syncthreads();
    epilogue_ln(sm, acc, 3, warp, lane);
    asm volatile("cp.async.wait_group 0;" ::: "memory");   // g3 (W3) done
    __syncthreads();

    // ---- stage 3: buf0, out = h @ fc3^T + b3 ----
    gemm128(sb, sb + OFF_W0, acc, warp, lane);
    {
        const int tig  = lane & 3;
        const int grp  = lane >> 2;
        const int mblk = (warp >> 1) << 5;
        const int nblk = (warp & 1) << 6;
        const float* bias = (const float*)(sm + OFF_VEC) + 6 * 128;
#pragma unroll
        for (int mi = 0; mi < 2; mi++) {
            const int r0 = mblk + grp + (mi << 4);
            const int r1 = r0 + 8;
            float* o0 = out + ((size_t)br * E_TOT + base + r0) * 128;
            float* o1 = o0 + (size_t)8 * 128;
#pragma unroll
            for (int nj = 0; nj < 8; nj++) {
                const int c = nblk + (nj << 3) + (tig << 1);
                const float b0 = bias[c], b1 = bias[c + 1];
                const float* a = acc[mi][nj];
                if (r0 < nvalid)
                    *(float2*)(o0 + c) = make_float2(a[0] + b0, a[1] + b1);
                if (r1 < nvalid)
                    *(float2*)(o1 + c) = make_float2(a[2] + b0, a[3] + b1);
            }
        }
    }
}

extern "C" void kernel_launch(void* const* d_in, const int* in_sizes, int n_in,
                              void* d_out, int out_size) {
    const float* x     = (const float*)d_in[0];
    const float* W1    = (const float*)d_in[1];
    const float* b1    = (const float*)d_in[2];
    const float* eln1w = (const float*)d_in[3];
    const float* eln1b = (const float*)d_in[4];
    const float* ef2w  = (const float*)d_in[5];
    const float* ef2b  = (const float*)d_in[6];
    const float* eln2w = (const float*)d_in[7];
    const float* eln2b = (const float*)d_in[8];
    const float* ef3w  = (const float*)d_in[9];
    const float* ef3b  = (const float*)d_in[10];
    const float* ln1w  = (const float*)d_in[11];
    const float* ln1b  = (const float*)d_in[12];
    const float* f2w   = (const float*)d_in[13];
    const float* f2b   = (const float*)d_in[14];
    const float* ln2w  = (const float*)d_in[15];
    const float* ln2b  = (const float*)d_in[16];
    const float* f3w   = (const float*)d_in[17];
    const float* f3b   = (const float*)d_in[18];
    float* out = (float*)d_out;

    cudaFuncSetAttribute(urmlp_kernel, cudaFuncAttributeMaxDynamicSharedMemorySize, SMEM_SZ);

    const int xblocks = (E_TOT * 32 + 255) / 256;
    prep_all<<<27 + xblocks, 256>>>(x, W1, ef2w, f2w, ef3w, f3w);

    const int tiles = (E_TOT + TE - 1) / TE;   // 1172
    urmlp_kernel<<<tiles * 9, NT, SMEM_SZ>>>(
        b1, eln1w, eln1b, ef2b, eln2w, eln2b, ef3b,
        ln1w, ln1b, f2b, ln2w, ln2b, f3b, out);
}

// round 16
// speedup vs baseline: 1.0751x; 1.0538x over previous
#include <cuda_runtime.h>
#include <cuda_fp16.h>
#include <cstdint>
#include <cstddef>

#define E_TOT 150000
#define TE    128         // rows per tile; CTA handles 2 tiles (256 rows)
#define NT    256         // 8 warps = 4 m-groups x 2 n-groups
#define SA    136         // fp16 padded row stride (elements)
#define RB    272         // row bytes

// ---- smem layout (bytes) ----
#define OFF_VEC   0                      // 7 x 128 f32 = 3584
#define OFF_PART0 3584                   // 2 x 128 float2 = 2048
#define OFF_PART1 5632                   // 2048
#define OFF_A0    7680                   // 128*272 = 34816
#define OFF_A1    42496                  // 34816
#define OFF_W     77312                  // 34816
#define SMEM_SZ   112128                 // -> 2 CTAs/SM

// pre-rounded weights: 27 matrices, fp16, padded layout identical to smem
__device__ __align__(16) __half g_w[27][128 * SA];
// pre-rounded x: fp16, linear [row][col]
__device__ __align__(16) __half g_x[(size_t)E_TOT * 128];

// ---------------------------------------------------------------------------
__device__ __forceinline__ uint32_t pkh(float a, float b) {
    __half2 t = __floats2half2_rn(a, b);
    return *(uint32_t*)&t;
}
__device__ __forceinline__ uint32_t s2u(const void* p) {
    uint32_t a;
    asm("{ .reg .u64 t; cvta.to.shared.u64 t, %1; cvt.u32.u64 %0, t; }" : "=r"(a) : "l"(p));
    return a;
}
__device__ __forceinline__ void cpa16(uint32_t saddr, const void* g) {
    asm volatile("cp.async.cg.shared.global [%0], [%1], 16;" :: "r"(saddr), "l"(g));
}
__device__ __forceinline__ void cpa_commit() { asm volatile("cp.async.commit_group;" ::: "memory"); }

__device__ __forceinline__ void mma16816(float d[4], const uint32_t a[4],
                                         uint32_t b0, uint32_t b1) {
    asm volatile(
        "mma.sync.aligned.m16n8k16.row.col.f32.f16.f16.f32 "
        "{%0,%1,%2,%3}, {%4,%5,%6,%7}, {%8,%9}, {%0,%1,%2,%3};\n"
        : "+f"(d[0]), "+f"(d[1]), "+f"(d[2]), "+f"(d[3])
        : "r"(a[0]), "r"(a[1]), "r"(a[2]), "r"(a[3]), "r"(b0), "r"(b1));
}
#define LDSM4(r, addr) \
    asm volatile("ldmatrix.sync.aligned.m8n8.x4.shared.b16 {%0,%1,%2,%3}, [%4];" \
        : "=r"((r)[0]), "=r"((r)[1]), "=r"((r)[2]), "=r"((r)[3]) : "r"(addr))

__device__ __forceinline__ float tanhf_fast(float x) {
    float r; asm("tanh.approx.f32 %0, %1;" : "=f"(r) : "f"(x)); return r;
}
__device__ __forceinline__ float silu(float y) {
    return y * fmaf(0.5f, tanhf_fast(0.5f * y), 0.5f);
}

// ---------------------------------------------------------------------------
// prep (single kernel): blocks [0,27) round weights; blocks [27,...) round x
// ---------------------------------------------------------------------------
__global__ void prep_all(const float* __restrict__ x,
                         const float* __restrict__ W1,
                         const float* __restrict__ ef2w, const float* __restrict__ f2w,
                         const float* __restrict__ ef3w, const float* __restrict__ f3w) {
    if (blockIdx.x < 27) {
        int m = blockIdx.x;
        const float* src;
        if (m < 9)       src = W1 + (size_t)m * 16384;
        else if (m < 18) { int b = m - 9;  src = b ? f2w + (size_t)(b - 1) * 16384 : ef2w; }
        else             { int b = m - 18; src = b ? f3w + (size_t)(b - 1) * 16384 : ef3w; }
        __half* w = g_w[m];
        for (int i = threadIdx.x; i < 16384; i += 256) {
            int r = i >> 7, c = i & 127;
            w[r * SA + c] = __float2half_rn(__ldg(src + i));
        }
        return;
    }
    size_t i = (size_t)(blockIdx.x - 27) * 256 + threadIdx.x;  // one float4 per thread
    if (i >= (size_t)E_TOT * 32) return;
    float4 v = __ldg((const float4*)x + i);
    uint2 uh;
    uh.x = pkh(v.x, v.y);
    uh.y = pkh(v.z, v.w);
    *(uint2*)(g_x + i * 4) = uh;
}

// ---------------------------------------------------------------------------
// 128x128x128 GEMM from smem via ldmatrix, m32n64 warp tiles:
// 8 warps = 4 m-groups (warp>>1) x 2 n-groups (warp&1).
// ---------------------------------------------------------------------------
__device__ __forceinline__ void gemm128(uint32_t abase, uint32_t wbase,
                                        float acc[2][8][4], int warp, int lane) {
#pragma unroll
    for (int mi = 0; mi < 2; mi++)
#pragma unroll
        for (int nj = 0; nj < 8; nj++)
#pragma unroll
            for (int j = 0; j < 4; j++) acc[mi][nj][j] = 0.f;

    const int mblk = (warp >> 1) << 5;
    const int nblk = (warp & 1) << 6;

    const int rs_a = (lane & 7) + (((lane >> 3) & 1) << 3);
    const uint32_t ka = (lane >> 4) << 4;
    const uint32_t a0 = abase + (mblk + rs_a) * RB + ka;           // m16 block 0
    const uint32_t a1 = a0 + 16 * RB;                              // m16 block 1
    const int rs_b = (lane & 7) + ((lane >> 4) << 3);
    const uint32_t kb = ((lane >> 3) & 1) << 4;
    const uint32_t bb = wbase + (nblk + rs_b) * RB + kb;           // n16 group base

#pragma unroll 1
    for (int ks = 0; ks < 8; ks++) {
        const uint32_t k0b = ks << 5;                              // 16 elems = 32B
        uint32_t ah0[4], ah1[4];
        uint32_t bf[4][4];
        LDSM4(ah0, a0 + k0b);
        LDSM4(ah1, a1 + k0b);
#pragma unroll
        for (int p = 0; p < 4; p++)
            LDSM4(bf[p], bb + p * (16 * RB) + k0b);

#pragma unroll
        for (int p = 0; p < 4; p++) {
            mma16816(acc[0][2 * p],     ah0, bf[p][0], bf[p][1]);
            mma16816(acc[0][2 * p + 1], ah0, bf[p][2], bf[p][3]);
            mma16816(acc[1][2 * p],     ah1, bf[p][0], bf[p][1]);
            mma16816(acc[1][2 * p + 1], ah1, bf[p][2], bf[p][3]);
        }
    }
}

// ---------------------------------------------------------------------------
// Epilogue stage 1: bias add + row stats. Ends with __syncthreads (also the
// "all gemm reads done" barrier for this tile). Returns m[4], inv[4].
// ---------------------------------------------------------------------------
__device__ __forceinline__ void epi_stats(char* sm, float acc[2][8][4], int vecb,
                                          int part_off, int warp, int lane,
                                          float m[4], float inv[4]) {
    const int tig  = lane & 3;
    const int grp  = lane >> 2;
    const int ngrp = warp & 1;
    const int mblk = (warp >> 1) << 5;
    const int nblk = ngrp << 6;

    const float* bias = (const float*)(sm + OFF_VEC) + vecb * 128;

    float s[4] = {0.f, 0.f, 0.f, 0.f};
    float q[4] = {0.f, 0.f, 0.f, 0.f};
#pragma unroll
    for (int mi = 0; mi < 2; mi++) {
#pragma unroll
        for (int nj = 0; nj < 8; nj++) {
            const int c = nblk + (nj << 3) + (tig << 1);
            const float b0 = bias[c], b1 = bias[c + 1];
            float* a = acc[mi][nj];
            a[0] += b0; a[1] += b1; a[2] += b0; a[3] += b1;
            s[2 * mi]     += a[0] + a[1];
            q[2 * mi]      = fmaf(a[0], a[0], fmaf(a[1], a[1], q[2 * mi]));
            s[2 * mi + 1] += a[2] + a[3];
            q[2 * mi + 1]  = fmaf(a[2], a[2], fmaf(a[3], a[3], q[2 * mi + 1]));
        }
    }
#pragma unroll
    for (int off = 1; off <= 2; off <<= 1) {
#pragma unroll
        for (int i = 0; i < 4; i++) {
            s[i] += __shfl_xor_sync(0xFFFFFFFFu, s[i], off);
            q[i] += __shfl_xor_sync(0xFFFFFFFFu, q[i], off);
        }
    }
    float2* part = (float2*)(sm + part_off);
    if (tig == 0) {
        part[ngrp * 128 + mblk + grp]      = make_float2(s[0], q[0]);
        part[ngrp * 128 + mblk + grp + 8]  = make_float2(s[1], q[1]);
        part[ngrp * 128 + mblk + grp + 16] = make_float2(s[2], q[2]);
        part[ngrp * 128 + mblk + grp + 24] = make_float2(s[3], q[3]);
    }
    __syncthreads();
#pragma unroll
    for (int i = 0; i < 4; i++) {
        const int row = mblk + grp + (i << 3);
        float2 p0 = part[row];
        float2 p1 = part[128 + row];
        const float ss = p0.x + p1.x, qq = p0.y + p1.y;
        m[i]   = ss * (1.0f / 128.0f);
        inv[i] = rsqrtf(fmaf(-m[i], m[i], qq * (1.0f / 128.0f)) + 1e-5f);
    }
}

// ---------------------------------------------------------------------------
// Epilogue stage 2: normalize + SiLU + fp16 store into act buffer.
// ---------------------------------------------------------------------------
__device__ __forceinline__ void epi_norm(char* sm, float acc[2][8][4], int vecb,
                                         int a_off, const float m[4], const float inv[4],
                                         int warp, int lane) {
    const int tig  = lane & 3;
    const int grp  = lane >> 2;
    const int mblk = (warp >> 1) << 5;
    const int nblk = (warp & 1) << 6;

    const float* vec = (const float*)(sm + OFF_VEC);
    const float* lw  = vec + vecb * 128 + 128;
    const float* lb  = lw + 128;

#pragma unroll
    for (int mi = 0; mi < 2; mi++) {
        const int i0 = 2 * mi, i1 = 2 * mi + 1;
        const int r0 = mblk + grp + (mi << 4);
        const int r1 = r0 + 8;
#pragma unroll
        for (int nj = 0; nj < 8; nj++) {
            const int c = nblk + (nj << 3) + (tig << 1);
            const float w0 = lw[c], w1 = lw[c + 1], c0 = lb[c], c1 = lb[c + 1];
            const float* a = acc[mi][nj];
            float y00 = silu((a[0] - m[i0]) * inv[i0] * w0 + c0);
            float y01 = silu((a[1] - m[i0]) * inv[i0] * w1 + c1);
            float y10 = silu((a[2] - m[i1]) * inv[i1] * w0 + c0);
            float y11 = silu((a[3] - m[i1]) * inv[i1] * w1 + c1);
            *(uint32_t*)(sm + a_off + r0 * RB + c * 2) = pkh(y00, y01);
            *(uint32_t*)(sm + a_off + r1 * RB + c * 2) = pkh(y10, y11);
        }
    }
}

// final output: bias + store to gmem
__device__ __forceinline__ void out_store(char* sm, float acc[2][8][4],
                                          float* __restrict__ out, size_t obase,
                                          int nvalid, int warp, int lane) {
    const int tig  = lane & 3;
    const int grp  = lane >> 2;
    const int mblk = (warp >> 1) << 5;
    const int nblk = (warp & 1) << 6;
    const float* bias = (const float*)(sm + OFF_VEC) + 6 * 128;
#pragma unroll
    for (int mi = 0; mi < 2; mi++) {
        const int r0 = mblk + grp + (mi << 4);
        const int r1 = r0 + 8;
        float* o0 = out + obase + (size_t)r0 * 128;
        float* o1 = o0 + (size_t)8 * 128;
#pragma unroll
        for (int nj = 0; nj < 8; nj++) {
            const int c = nblk + (nj << 3) + (tig << 1);
            const float b0 = bias[c], b1 = bias[c + 1];
            const float* a = acc[mi][nj];
            if (r0 < nvalid)
                *(float2*)(o0 + c) = make_float2(a[0] + b0, a[1] + b1);
            if (r1 < nvalid)
                *(float2*)(o1 + c) = make_float2(a[2] + b0, a[3] + b1);
        }
    }
}

__device__ __forceinline__ void cp_weights(uint32_t sdst, int m, int tid) {
    const char* g = (const char*)g_w[m];               // 34816B fp16
    for (int i = tid; i < 34816 / 16; i += NT)
        cpa16(sdst + i * 16, g + (size_t)i * 16);
    cpa_commit();
}

__device__ __forceinline__ void cp_xtile(uint32_t adst, char* sm_a, int base,
                                         int nvalid, int tid) {
    for (int i = tid; i < TE * 16; i += NT) {           // 16 x 16B chunks per row
        const int row = i >> 4, ch = i & 15;
        if (row < nvalid) {
            cpa16(adst + row * RB + ch * 16, g_x + (size_t)(base + row) * 128 + ch * 8);
        } else {
            *(uint4*)(sm_a + row * RB + ch * 16) = make_uint4(0, 0, 0, 0);
        }
    }
    cpa_commit();
}

// ---------------------------------------------------------------------------
extern __shared__ char smraw[];

__global__ void __launch_bounds__(NT, 2)
urmlp_kernel(const float* __restrict__ b1c,
             const float* __restrict__ eln1w, const float* __restrict__ eln1b,
             const float* __restrict__ ef2b,
             const float* __restrict__ eln2w, const float* __restrict__ eln2b,
             const float* __restrict__ ef3b,
             const float* __restrict__ ln1w,  const float* __restrict__ ln1b,
             const float* __restrict__ f2b,
             const float* __restrict__ ln2w,  const float* __restrict__ ln2b,
             const float* __restrict__ f3b,
             float* __restrict__ out)
{
    char* sm = smraw;
    const int tid  = threadIdx.x;
    const int warp = tid >> 5;
    const int lane = tid & 31;
    const int bid  = blockIdx.x;
    const int pair = bid / 9;
    const int br   = bid - pair * 9;
    const int baseA = pair * (2 * TE);
    const int baseB = baseA + TE;
    const int nvalA = min(TE, E_TOT - baseA);
    const int nvalB = min(TE, E_TOT - baseB);
    const uint32_t sb = s2u(sm);
    const uint32_t aA = sb + OFF_A0, aB = sb + OFF_A1, wB = sb + OFF_W;

    // g0: W1; g1: xA; g2: xB
    cp_weights(wB, br, tid);
    cp_xtile(aA, sm + OFF_A0, baseA, nvalA, tid);
    cp_xtile(aB, sm + OFF_A1, baseB, nvalB, tid);

    // per-branch vectors: [b1, lw1, lb1, b2, lw2, lb2, b3]
    if (tid < 128) {
        float* vec = (float*)(sm + OFF_VEC);
        const float* s0 = b1c + br * 128;
        const float* s1 = br ? ln1w + (br - 1) * 128 : eln1w;
        const float* s2 = br ? ln1b + (br - 1) * 128 : eln1b;
        const float* s3 = br ? f2b  + (br - 1) * 128 : ef2b;
        const float* s4 = br ? ln2w + (br - 1) * 128 : eln2w;
        const float* s5 = br ? ln2b + (br - 1) * 128 : eln2b;
        const float* s6 = br ? f3b  + (br - 1) * 128 : ef3b;
        vec[0 * 128 + tid] = __ldg(s0 + tid);
        vec[1 * 128 + tid] = __ldg(s1 + tid);
        vec[2 * 128 + tid] = __ldg(s2 + tid);
        vec[3 * 128 + tid] = __ldg(s3 + tid);
        vec[4 * 128 + tid] = __ldg(s4 + tid);
        vec[5 * 128 + tid] = __ldg(s5 + tid);
        vec[6 * 128 + tid] = __ldg(s6 + tid);
    }

    asm volatile("cp.async.wait_group 1;" ::: "memory");   // W1, xA done (xB in flight)
    __syncthreads();                                        // S0

    float acc[2][8][4];
    float m[4], inv[4];

    // ================= super-stage 1 (W1) =================
    gemm128(aA, wB, acc, warp, lane);
    epi_stats(sm, acc, 0, OFF_PART0, warp, lane, m, inv);   // S1 (gemm1A reads done)
    epi_norm(sm, acc, 0, OFF_A0, m, inv, warp, lane);       // actA -> A0
    asm volatile("cp.async.wait_group 0;" ::: "memory");    // xB resident
    gemm128(aB, wB, acc, warp, lane);
    epi_stats(sm, acc, 0, OFF_PART1, warp, lane, m, inv);   // S2 (all W1 reads done)
    cp_weights(wB, 9 + br, tid);                            // g3: W2 over W1
    epi_norm(sm, acc, 0, OFF_A1, m, inv, warp, lane);       // actB -> A1
    asm volatile("cp.async.wait_group 0;" ::: "memory");    // W2 resident
    __syncthreads();                                        // S3 (W2 + actB visible)

    // ================= super-stage 2 (W2) =================
    gemm128(aA, wB, acc, warp, lane);
    epi_stats(sm, acc, 3, OFF_PART0, warp, lane, m, inv);   // S4
    epi_norm(sm, acc, 3, OFF_A0, m, inv, warp, lane);
    gemm128(aB, wB, acc, warp, lane);
    epi_stats(sm, acc, 3, OFF_PART1, warp, lane, m, inv);   // S5 (all W2 reads done)
    cp_weights(wB, 18 + br, tid);                           // g4: W3 over W2
    epi_norm(sm, acc, 3, OFF_A1, m, inv, warp, lane);
    asm volatile("cp.async.wait_group 0;" ::: "memory");    // W3 resident
    __syncthreads();                                        // S6

    // ================= super-stage 3 (W3) -> out =================
    gemm128(aA, wB, acc, warp, lane);
    out_store(sm, acc, out, ((size_t)br * E_TOT + baseA) * 128, nvalA, warp, lane);
    gemm128(aB, wB, acc, warp, lane);
    out_store(sm, acc, out, ((size_t)br * E_TOT + baseB) * 128, nvalB, warp, lane);
}

extern "C" void kernel_launch(void* const* d_in, const int* in_sizes, int n_in,
                              void* d_out, int out_size) {
    const float* x     = (const float*)d_in[0];
    const float* W1    = (const float*)d_in[1];
    const float* b1    = (const float*)d_in[2];
    const float* eln1w = (const float*)d_in[3];
    const float* eln1b = (const float*)d_in[4];
    const float* ef2w  = (const float*)d_in[5];
    const float* ef2b  = (const float*)d_in[6];
    const float* eln2w = (const float*)d_in[7];
    const float* eln2b = (const float*)d_in[8];
    const float* ef3w  = (const float*)d_in[9];
    const float* ef3b  = (const float*)d_in[10];
    const float* ln1w  = (const float*)d_in[11];
    const float* ln1b  = (const float*)d_in[12];
    const float* f2w   = (const float*)d_in[13];
    const float* f2b   = (const float*)d_in[14];
    const float* ln2w  = (const float*)d_in[15];
    const float* ln2b  = (const float*)d_in[16];
    const float* f3w   = (const float*)d_in[17];
    const float* f3b   = (const float*)d_in[18];
    float* out = (float*)d_out;

    cudaFuncSetAttribute(urmlp_kernel, cudaFuncAttributeMaxDynamicSharedMemorySize, SMEM_SZ);

    const int xblocks = (E_TOT * 32 + 255) / 256;
    prep_all<<<27 + xblocks, 256>>>(x, W1, ef2w, f2w, ef3w, f3w);

    const int pairs = (E_TOT + 2 * TE - 1) / (2 * TE);   // 586
    urmlp_kernel<<<pairs * 9, NT, SMEM_SZ>>>(
        b1, eln1w, eln1b, ef2b, eln2w, eln2b, ef3b,
        ln1w, ln1b, f2b, ln2w, ln2b, f3b, out);
}